// round 1
// baseline (speedup 1.0000x reference)
#include <cuda_runtime.h>
#include <math.h>

// ---------------------------------------------------------------------------
// SwinV2 block: B=32, H=W=48, C=384, NH=12, HD=32, WS=12, N=144, SHIFT=6
// ---------------------------------------------------------------------------
namespace {
constexpr int kB = 32;
constexpr int kH = 48;
constexpr int kW = 48;
constexpr int kC = 384;
constexpr int kNH = 12;
constexpr int kHD = 32;
constexpr int kWS = 12;
constexpr int kN = 144;          // tokens per window
constexpr int kSHIFT = 6;
constexpr int kM = 73728;        // total window tokens = 512 windows * 144
constexpr long kSLOT = 28311552; // kM * kC
}

// scratch: slot0 = q / proj_out / fc2_out
//          slot1 = k / x1
//          slot2 = v ; slot3 = attn_out ; h1 (fc1 out, 4 slots) spans 2..5
__device__ float g_scratch[6 * 28311552ULL];
__device__ float g_btab[529 * 12];
__device__ float g_bias[12 * 144 * 144];

// window token m -> source/destination row in the (B, 48, 48) image.
// gather (shift -6 + partition) and scatter (reverse + shift +6) are the same map.
__device__ __forceinline__ int win_src_row(int m) {
    int wi = m / kN, t = m - wi * kN;
    int b  = wi >> 4;
    int wh = (wi >> 2) & 3;
    int ww = wi & 3;
    int th = t / kWS, tw = t - th * kWS;
    int sh = wh * kWS + th + kSHIFT; if (sh >= kH) sh -= kH;
    int sw = ww * kWS + tw + kSHIFT; if (sw >= kW) sw -= kW;
    return (b * kH + sh) * kW + sw;
}

// ---------------------------------------------------------------------------
// K1: CPB MLP -> 16*sigmoid table (529 x 12)
// ---------------------------------------------------------------------------
__global__ void cpb_kernel(const float* __restrict__ table,
                           const float* __restrict__ w1,
                           const float* __restrict__ b1,
                           const float* __restrict__ w2) {
    __shared__ float hid[512];
    int e = blockIdx.x;
    int tid = threadIdx.x;
    float t0 = table[e * 2 + 0], t1 = table[e * 2 + 1];
    hid[tid] = fmaxf(0.f, fmaf(t0, w1[tid], fmaf(t1, w1[512 + tid], b1[tid])));
    __syncthreads();
    if (tid < 12) {
        float s = 0.f;
        #pragma unroll 8
        for (int i = 0; i < 512; i++) s = fmaf(hid[i], w2[i * 12 + tid], s);
        g_btab[e * 12 + tid] = 16.f / (1.f + expf(-s));
    }
}

// K1b: expand via relative_position_index -> (12, 144, 144)
__global__ void bias_expand_kernel(const int* __restrict__ rpi) {
    int idx = blockIdx.x * 256 + threadIdx.x;
    if (idx >= 12 * 144 * 144) return;
    int h  = idx / (144 * 144);
    int rj = idx - h * (144 * 144);
    g_bias[idx] = g_btab[rpi[rj] * 12 + h];
}

// ---------------------------------------------------------------------------
// SGEMM: 128x128 tile, BK=8, 8x8 per thread, 256 threads.
// MODE 0: qkv (A gathered from x; scatter to q/k/v slots, q/v bias)
// MODE 1: plain + bias (proj, fc2)
// MODE 2: bias + exact GELU (fc1)
// ---------------------------------------------------------------------------
template <int MODE, int Ncols, int Kdim>
__global__ void __launch_bounds__(256) gemm_kernel(
    const float* __restrict__ A_in, const float* __restrict__ Wm,
    const float* __restrict__ bias, const float* __restrict__ bias2,
    float* __restrict__ Cout) {
    constexpr int BM = 128, BN = 128, BK = 8;
    __shared__ float As[BK][BM];
    __shared__ float Bs[BK][BN];
    int tid = threadIdx.x;
    int bx = blockIdx.x, by = blockIdx.y;

    int aRow = tid >> 1;
    int aCol = (tid & 1) << 2;
    int bRow = tid >> 5;
    int bCol = (tid & 31) << 2;

    int gRow = by * BM + aRow;
    long arow = (MODE == 0) ? (long)win_src_row(gRow) : (long)gRow;
    const float* Aptr = A_in + arow * Kdim + aCol;
    const float* Bptr = Wm + (long)bRow * Ncols + bx * BN + bCol;

    float acc[8][8];
    #pragma unroll
    for (int i = 0; i < 8; i++)
        #pragma unroll
        for (int j = 0; j < 8; j++) acc[i][j] = 0.f;

    int tx = tid & 15, ty = tid >> 4;

    for (int k0 = 0; k0 < Kdim; k0 += BK) {
        float4 a = *(const float4*)Aptr; Aptr += BK;
        float4 b = *(const float4*)Bptr; Bptr += (long)BK * Ncols;
        As[aCol + 0][aRow] = a.x;
        As[aCol + 1][aRow] = a.y;
        As[aCol + 2][aRow] = a.z;
        As[aCol + 3][aRow] = a.w;
        *(float4*)&Bs[bRow][bCol] = b;
        __syncthreads();
        #pragma unroll
        for (int kk = 0; kk < BK; kk++) {
            float ra[8], rb[8];
            *(float4*)&ra[0] = *(const float4*)&As[kk][ty * 8];
            *(float4*)&ra[4] = *(const float4*)&As[kk][ty * 8 + 4];
            *(float4*)&rb[0] = *(const float4*)&Bs[kk][tx * 8];
            *(float4*)&rb[4] = *(const float4*)&Bs[kk][tx * 8 + 4];
            #pragma unroll
            for (int i = 0; i < 8; i++)
                #pragma unroll
                for (int j = 0; j < 8; j++) acc[i][j] = fmaf(ra[i], rb[j], acc[i][j]);
        }
        __syncthreads();
    }

    int row0 = by * BM + ty * 8;
    int col0 = bx * BN + tx * 8;

    if (MODE == 0) {
        #pragma unroll
        for (int i = 0; i < 8; i++) {
            int row = row0 + i;
            int wi = row / kN, t = row - wi * kN;
            #pragma unroll
            for (int j = 0; j < 8; j++) {
                int col = col0 + j;
                int part = col / kC;
                int c = col - part * kC;
                float bv = (part == 0) ? bias[c] : ((part == 2) ? bias2[c] : 0.f);
                float v = acc[i][j] + bv;
                int h = c >> 5, d = c & 31;
                g_scratch[(long)part * kSLOT +
                          (((long)(wi * kNH + h)) * kN + t) * kHD + d] = v;
            }
        }
    } else {
        #pragma unroll
        for (int i = 0; i < 8; i++) {
            long row = row0 + i;
            #pragma unroll
            for (int j = 0; j < 8; j++) {
                int col = col0 + j;
                float v = acc[i][j] + bias[col];
                if (MODE == 2)
                    v = 0.5f * v * (1.f + erff(v * 0.70710678118654752440f));
                Cout[row * Ncols + col] = v;
            }
        }
    }
}

// ---------------------------------------------------------------------------
// K3: cosine attention, one block per (window, head). 128 threads.
// ---------------------------------------------------------------------------
__global__ void __launch_bounds__(128) attn_kernel(
    const float* __restrict__ mask, const float* __restrict__ logit_scale) {
    __shared__ float ks[144][32];
    __shared__ float vs[144][32];
    int bh = blockIdx.x;            // wi*12 + h
    int wi = bh / kNH, h = bh - wi * kNH;
    int tid = threadIdx.x;

    const float* qg = g_scratch + 0 * kSLOT + (long)bh * kN * kHD;
    const float* kg = g_scratch + 1 * kSLOT + (long)bh * kN * kHD;
    const float* vg = g_scratch + 2 * kSLOT + (long)bh * kN * kHD;
    float* outp = g_scratch + 3 * kSLOT;

    for (int i = tid; i < kN * kHD; i += 128) {
        (&ks[0][0])[i] = kg[i];
        (&vs[0][0])[i] = vg[i];
    }
    __syncthreads();
    // normalize k rows
    for (int r = tid; r < kN; r += 128) {
        float s = 0.f;
        #pragma unroll
        for (int d = 0; d < kHD; d++) s = fmaf(ks[r][d], ks[r][d], s);
        float inv = 1.f / fmaxf(sqrtf(s), 1e-12f);
        #pragma unroll
        for (int d = 0; d < kHD; d++) ks[r][d] *= inv;
    }
    __syncthreads();

    float scale = expf(fminf(logit_scale[h], 4.605170185988092f)); // log(100)
    const float* maskp = mask + (long)(wi & 15) * kN * kN;
    const float* biasp = g_bias + (long)h * kN * kN;

    for (int r = tid; r < kN; r += 128) {
        float qr[32];
        float s = 0.f;
        #pragma unroll
        for (int d = 0; d < kHD; d++) {
            qr[d] = qg[r * kHD + d];
            s = fmaf(qr[d], qr[d], s);
        }
        float inv = scale / fmaxf(sqrtf(s), 1e-12f);
        #pragma unroll
        for (int d = 0; d < kHD; d++) qr[d] *= inv;

        float p[144];
        float mx = -1e30f;
        const float* br = biasp + r * kN;
        const float* mr = maskp + r * kN;
        for (int j = 0; j < kN; j++) {
            float t = 0.f;
            #pragma unroll
            for (int d = 0; d < kHD; d++) t = fmaf(qr[d], ks[j][d], t);
            t += br[j] + mr[j];
            p[j] = t;
            mx = fmaxf(mx, t);
        }
        float sum = 0.f;
        float o[32];
        #pragma unroll
        for (int d = 0; d < kHD; d++) o[d] = 0.f;
        for (int j = 0; j < kN; j++) {
            float pj = expf(p[j] - mx);
            sum += pj;
            #pragma unroll
            for (int d = 0; d < kHD; d++) o[d] = fmaf(pj, vs[j][d], o[d]);
        }
        float rs = 1.f / sum;
        float* op = outp + ((long)(wi * kN + r)) * kC + h * kHD;
        #pragma unroll
        for (int d = 0; d < kHD; d++) op[d] = o[d] * rs;
    }
}

// ---------------------------------------------------------------------------
// LN + residual (optionally scattering window order -> image order)
// out[dst] = resid[dst] + LN(src[m]) * g + b
// ---------------------------------------------------------------------------
template <bool SCATTER>
__global__ void __launch_bounds__(128) ln_res_kernel(
    const float* __restrict__ src, const float* __restrict__ resid,
    const float* __restrict__ gam, const float* __restrict__ bet,
    float* __restrict__ out) {
    int m = blockIdx.x;
    int dst = SCATTER ? win_src_row(m) : m;
    const float* row = src + (long)m * kC;
    int tid = threadIdx.x;
    float v0 = row[tid], v1 = row[tid + 128], v2 = row[tid + 256];
    float s = v0 + v1 + v2;
    float s2 = v0 * v0 + v1 * v1 + v2 * v2;
    #pragma unroll
    for (int o = 16; o > 0; o >>= 1) {
        s  += __shfl_xor_sync(0xffffffffu, s, o);
        s2 += __shfl_xor_sync(0xffffffffu, s2, o);
    }
    __shared__ float sh[8];
    int wid = tid >> 5, lane = tid & 31;
    if (lane == 0) { sh[wid] = s; sh[4 + wid] = s2; }
    __syncthreads();
    s  = sh[0] + sh[1] + sh[2] + sh[3];
    s2 = sh[4] + sh[5] + sh[6] + sh[7];
    float mean = s * (1.f / 384.f);
    float var = s2 * (1.f / 384.f) - mean * mean;
    float rstd = rsqrtf(var + 1e-5f);
    const float* rrow = resid + (long)dst * kC;
    float* orow = out + (long)dst * kC;
    orow[tid]       = rrow[tid]       + (v0 - mean) * rstd * gam[tid]       + bet[tid];
    orow[tid + 128] = rrow[tid + 128] + (v1 - mean) * rstd * gam[tid + 128] + bet[tid + 128];
    orow[tid + 256] = rrow[tid + 256] + (v2 - mean) * rstd * gam[tid + 256] + bet[tid + 256];
}

// ---------------------------------------------------------------------------
extern "C" void kernel_launch(void* const* d_in, const int* in_sizes, int n_in,
                              void* d_out, int out_size) {
    const float* x    = (const float*)d_in[0];
    const float* tab  = (const float*)d_in[1];
    const int*   rpi  = (const int*)  d_in[2];
    const float* mask = (const float*)d_in[3];
    const float* qkvw = (const float*)d_in[4];
    const float* qb   = (const float*)d_in[5];
    const float* vb   = (const float*)d_in[6];
    const float* lsc  = (const float*)d_in[7];
    const float* w1   = (const float*)d_in[8];
    const float* b1   = (const float*)d_in[9];
    const float* w2   = (const float*)d_in[10];
    const float* pw   = (const float*)d_in[11];
    const float* pb   = (const float*)d_in[12];
    const float* n1g  = (const float*)d_in[13];
    const float* n1b  = (const float*)d_in[14];
    const float* n2g  = (const float*)d_in[15];
    const float* n2b  = (const float*)d_in[16];
    const float* f1w  = (const float*)d_in[17];
    const float* f1b  = (const float*)d_in[18];
    const float* f2w  = (const float*)d_in[19];
    const float* f2b  = (const float*)d_in[20];
    float* out = (float*)d_out;

    float* scratch = nullptr;
    cudaGetSymbolAddress((void**)&scratch, g_scratch);

    // 1. CPB bias table + expansion
    cpb_kernel<<<529, 512>>>(tab, w1, b1, w2);
    bias_expand_kernel<<<(12 * 144 * 144 + 255) / 256, 256>>>(rpi);

    // 2. QKV GEMM (gathered A) -> q/k/v slots
    {
        dim3 g(1152 / 128, kM / 128);
        gemm_kernel<0, 1152, 384><<<g, 256>>>(x, qkvw, qb, vb, scratch);
    }

    // 3. attention -> slot3
    attn_kernel<<<512 * kNH, 128>>>(mask, lsc);

    // 4. proj GEMM: slot3 -> slot0
    {
        dim3 g(384 / 128, kM / 128);
        gemm_kernel<1, 384, 384><<<g, 256>>>(scratch + 3 * kSLOT, pw, pb, nullptr,
                                             scratch + 0 * kSLOT);
    }

    // 5. LN + residual + scatter: slot0 (+x) -> slot1 (x1)
    ln_res_kernel<true><<<kM, 128>>>(scratch + 0 * kSLOT, x, n1g, n1b,
                                     scratch + 1 * kSLOT);

    // 6. fc1 + GELU: slot1 -> slot2 (4 slots)
    {
        dim3 g(1536 / 128, kM / 128);
        gemm_kernel<2, 1536, 384><<<g, 256>>>(scratch + 1 * kSLOT, f1w, f1b, nullptr,
                                              scratch + 2 * kSLOT);
    }

    // 7. fc2: slot2 -> slot0
    {
        dim3 g(384 / 128, kM / 128);
        gemm_kernel<1, 384, 1536><<<g, 256>>>(scratch + 2 * kSLOT, f2w, f2b, nullptr,
                                              scratch + 0 * kSLOT);
    }

    // 8. final LN + residual -> out
    ln_res_kernel<false><<<kM, 128>>>(scratch + 0 * kSLOT, scratch + 1 * kSLOT,
                                      n2g, n2b, out);
}

// round 2
// speedup vs baseline: 2.0791x; 2.0791x over previous
#include <cuda_runtime.h>
#include <math.h>
#include <stdint.h>

// ---------------------------------------------------------------------------
// SwinV2 block: B=32, H=W=48, C=384, NH=12, HD=32, WS=12, N=144, SHIFT=6
// ---------------------------------------------------------------------------
namespace {
constexpr int kH = 48;
constexpr int kW = 48;
constexpr int kC = 384;
constexpr int kNH = 12;
constexpr int kHD = 32;
constexpr int kWS = 12;
constexpr int kN = 144;          // tokens per window
constexpr int kSHIFT = 6;
constexpr int kM = 73728;        // total window tokens = 512 windows * 144
constexpr long kSLOT = 28311552; // kM * kC
}

// scratch: slot0 = q / proj_out / fc2_out
//          slot1 = k / x1
//          slot2 = v ; slot3 = attn_out ; h1 (fc1 out, 4 slots) spans 2..5
__device__ float g_scratch[6 * 28311552ULL];
__device__ float g_btab[529 * 12];
__device__ float g_bias2[16 * 12 * 144 * 144];  // bias + mask, combined

// window token m -> source/destination row in the (B, 48, 48) image.
__device__ __forceinline__ int win_src_row(int m) {
    int wi = m / kN, t = m - wi * kN;
    int b  = wi >> 4;
    int wh = (wi >> 2) & 3;
    int ww = wi & 3;
    int th = t / kWS, tw = t - th * kWS;
    int sh = wh * kWS + th + kSHIFT; if (sh >= kH) sh -= kH;
    int sw = ww * kWS + tw + kSHIFT; if (sw >= kW) sw -= kW;
    return (b * kH + sh) * kW + sw;
}

// ---------------------------------------------------------------------------
// K1: CPB MLP -> 16*sigmoid table (529 x 12)
// ---------------------------------------------------------------------------
__global__ void cpb_kernel(const float* __restrict__ table,
                           const float* __restrict__ w1,
                           const float* __restrict__ b1,
                           const float* __restrict__ w2) {
    __shared__ float hid[512];
    int e = blockIdx.x;
    int tid = threadIdx.x;
    float t0 = table[e * 2 + 0], t1 = table[e * 2 + 1];
    hid[tid] = fmaxf(0.f, fmaf(t0, w1[tid], fmaf(t1, w1[512 + tid], b1[tid])));
    __syncthreads();
    if (tid < 12) {
        float s = 0.f;
        #pragma unroll 8
        for (int i = 0; i < 512; i++) s = fmaf(hid[i], w2[i * 12 + tid], s);
        g_btab[e * 12 + tid] = 16.f / (1.f + expf(-s));
    }
}

// K1b: expand via rpi + fold attention mask -> (16, 12, 144, 144)
__global__ void bias_expand_kernel(const int* __restrict__ rpi,
                                   const float* __restrict__ mask) {
    int idx = blockIdx.x * 256 + threadIdx.x;
    if (idx >= 16 * 12 * 144 * 144) return;
    int rj = idx % (144 * 144);
    int wh = idx / (144 * 144);
    int h = wh % 12, wt = wh / 12;
    g_bias2[idx] = g_btab[rpi[rj] * 12 + h] + mask[wt * 144 * 144 + rj];
}

// ---------------------------------------------------------------------------
// TF32 tensor-core GEMM: 128x128 tile, BK=16, 256 threads (8 warps, 4x2),
// each warp 32x64 via mma.sync.m16n8k8.tf32.
// MODE 0: qkv (A gathered from x; scatter to q/k/v slots, q/v bias)
// MODE 1: plain + bias (proj, fc2)
// MODE 2: bias + exact GELU (fc1)
// ---------------------------------------------------------------------------
__device__ __forceinline__ uint32_t f2tf(float x) {
    uint32_t u; asm("cvt.rna.tf32.f32 %0, %1;" : "=r"(u) : "f"(x)); return u;
}
__device__ __forceinline__ void mma8(float* c, const uint32_t* a, const uint32_t* b) {
    asm volatile("mma.sync.aligned.m16n8k8.row.col.f32.tf32.tf32.f32 "
        "{%0,%1,%2,%3},{%4,%5,%6,%7},{%8,%9},{%0,%1,%2,%3};"
        : "+f"(c[0]), "+f"(c[1]), "+f"(c[2]), "+f"(c[3])
        : "r"(a[0]), "r"(a[1]), "r"(a[2]), "r"(a[3]), "r"(b[0]), "r"(b[1]));
}

__device__ __forceinline__ float gelu_exact(float v) {
    return 0.5f * v * (1.f + erff(v * 0.70710678118654752440f));
}

__device__ __forceinline__ void qkv_store(int row, int col, float v,
                                          const float* qb, const float* vb) {
    int wi = row / kN, tk = row - wi * kN;
    int part = col / kC, c = col - part * kC;
    float bv = (part == 0) ? qb[c] : (part == 2 ? vb[c] : 0.f);
    g_scratch[(long)part * kSLOT +
              (((long)(wi * kNH + (c >> 5))) * kN + tk) * kHD + (c & 31)] = v + bv;
}

template <int MODE, int Ncols, int Kdim>
__global__ void __launch_bounds__(256) gemm_tf32(
    const float* __restrict__ A_in, const float* __restrict__ Wm,
    const float* __restrict__ bias, const float* __restrict__ bias2,
    float* __restrict__ Cout) {
    constexpr int ST = 136;  // stride mod 32 == 8 -> conflict-free frag loads
    __shared__ uint32_t As[16 * ST];  // As[k][m]
    __shared__ uint32_t Bs[16 * ST];  // Bs[k][n]
    int tid = threadIdx.x;
    int bx = blockIdx.x, by = blockIdx.y;
    int warp = tid >> 5, lane = tid & 31;
    int g = lane >> 2, t = lane & 3;
    int wm = (warp & 3) * 32, wn = (warp >> 2) * 64;

    // A global loads: 2 rows/thread, one float4 each
    int alr0 = tid >> 2;          // local rows alr0, alr0+64
    int acol = (tid & 3) * 4;
    long ar0, ar1;
    {
        int gr0 = by * 128 + alr0, gr1 = gr0 + 64;
        ar0 = (MODE == 0) ? (long)win_src_row(gr0) : (long)gr0;
        ar1 = (MODE == 0) ? (long)win_src_row(gr1) : (long)gr1;
    }
    // B global loads: rows blr, blr+8, one float4 each
    int blr = tid >> 5;
    int bcol = lane * 4;
    const float* Bp = Wm + (long)blr * Ncols + bx * 128 + bcol;

    float acc[2][8][4];
    #pragma unroll
    for (int i = 0; i < 2; i++)
        #pragma unroll
        for (int j = 0; j < 8; j++)
            #pragma unroll
            for (int q = 0; q < 4; q++) acc[i][j][q] = 0.f;

    for (int k0 = 0; k0 < Kdim; k0 += 16) {
        float4 av0 = *(const float4*)(A_in + ar0 * Kdim + k0 + acol);
        float4 av1 = *(const float4*)(A_in + ar1 * Kdim + k0 + acol);
        float4 bv0 = *(const float4*)(Bp + (long)k0 * Ncols);
        float4 bv1 = *(const float4*)(Bp + (long)(k0 + 8) * Ncols);
        __syncthreads();
        As[(acol + 0) * ST + alr0] = f2tf(av0.x);
        As[(acol + 1) * ST + alr0] = f2tf(av0.y);
        As[(acol + 2) * ST + alr0] = f2tf(av0.z);
        As[(acol + 3) * ST + alr0] = f2tf(av0.w);
        As[(acol + 0) * ST + alr0 + 64] = f2tf(av1.x);
        As[(acol + 1) * ST + alr0 + 64] = f2tf(av1.y);
        As[(acol + 2) * ST + alr0 + 64] = f2tf(av1.z);
        As[(acol + 3) * ST + alr0 + 64] = f2tf(av1.w);
        uint4 ub0 = make_uint4(f2tf(bv0.x), f2tf(bv0.y), f2tf(bv0.z), f2tf(bv0.w));
        uint4 ub1 = make_uint4(f2tf(bv1.x), f2tf(bv1.y), f2tf(bv1.z), f2tf(bv1.w));
        *(uint4*)&Bs[blr * ST + bcol] = ub0;
        *(uint4*)&Bs[(blr + 8) * ST + bcol] = ub1;
        __syncthreads();

        #pragma unroll
        for (int kk = 0; kk < 16; kk += 8) {
            uint32_t af[2][4];
            #pragma unroll
            for (int mt = 0; mt < 2; mt++) {
                int m0 = wm + mt * 16 + g;
                af[mt][0] = As[(kk + t) * ST + m0];
                af[mt][1] = As[(kk + t) * ST + m0 + 8];
                af[mt][2] = As[(kk + t + 4) * ST + m0];
                af[mt][3] = As[(kk + t + 4) * ST + m0 + 8];
            }
            uint32_t bf[8][2];
            #pragma unroll
            for (int nt = 0; nt < 8; nt++) {
                int n0 = wn + nt * 8 + g;
                bf[nt][0] = Bs[(kk + t) * ST + n0];
                bf[nt][1] = Bs[(kk + t + 4) * ST + n0];
            }
            #pragma unroll
            for (int mt = 0; mt < 2; mt++)
                #pragma unroll
                for (int nt = 0; nt < 8; nt++)
                    mma8(acc[mt][nt], af[mt], bf[nt]);
        }
    }

    int gr = by * 128 + wm + g;
    int gc = bx * 128 + wn + 2 * t;
    #pragma unroll
    for (int mt = 0; mt < 2; mt++) {
        int r0 = gr + mt * 16;
        #pragma unroll
        for (int nt = 0; nt < 8; nt++) {
            int c0 = gc + nt * 8;
            if (MODE == 0) {
                qkv_store(r0,     c0,     acc[mt][nt][0], bias, bias2);
                qkv_store(r0,     c0 + 1, acc[mt][nt][1], bias, bias2);
                qkv_store(r0 + 8, c0,     acc[mt][nt][2], bias, bias2);
                qkv_store(r0 + 8, c0 + 1, acc[mt][nt][3], bias, bias2);
            } else {
                float b0 = bias[c0], b1 = bias[c0 + 1];
                float2 v;
                v.x = acc[mt][nt][0] + b0; v.y = acc[mt][nt][1] + b1;
                if (MODE == 2) { v.x = gelu_exact(v.x); v.y = gelu_exact(v.y); }
                *(float2*)&Cout[(long)r0 * Ncols + c0] = v;
                v.x = acc[mt][nt][2] + b0; v.y = acc[mt][nt][3] + b1;
                if (MODE == 2) { v.x = gelu_exact(v.x); v.y = gelu_exact(v.y); }
                *(float2*)&Cout[(long)(r0 + 8) * Ncols + c0] = v;
            }
        }
    }
}

// ---------------------------------------------------------------------------
// K3: cosine attention, one block per (window, head). 160 threads, 1 row each.
// Fixed softmax stabilizer: logits <= scale + 16, so mx = scale+16 is valid.
// ---------------------------------------------------------------------------
__global__ void __launch_bounds__(160) attn_kernel(const float* __restrict__ lsc) {
    __shared__ float ks[144 * 32];
    __shared__ float vs[144 * 32];
    int bh = blockIdx.x;            // wi*12 + h
    int wi = bh / kNH, h = bh - wi * kNH;
    int tid = threadIdx.x;

    const float* qg = g_scratch + 0 * kSLOT + (long)bh * kN * kHD;
    const float* kg = g_scratch + 1 * kSLOT + (long)bh * kN * kHD;
    const float* vg = g_scratch + 2 * kSLOT + (long)bh * kN * kHD;

    for (int i = tid; i < kN * kHD; i += 160) {
        ks[i] = kg[i];
        vs[i] = vg[i];
    }
    __syncthreads();
    if (tid < kN) {
        float s = 0.f;
        #pragma unroll
        for (int d = 0; d < kHD; d++) s = fmaf(ks[tid * 32 + d], ks[tid * 32 + d], s);
        float inv = 1.f / fmaxf(sqrtf(s), 1e-12f);
        #pragma unroll
        for (int d = 0; d < kHD; d++) ks[tid * 32 + d] *= inv;
    }
    __syncthreads();

    if (tid < kN) {
        int r = tid;
        float scale = __expf(fminf(lsc[h], 4.605170185988092f)); // log(100)
        float qr[32];
        float s = 0.f;
        #pragma unroll
        for (int d = 0; d < kHD; d++) {
            qr[d] = qg[r * kHD + d];
            s = fmaf(qr[d], qr[d], s);
        }
        float inv = scale / fmaxf(sqrtf(s), 1e-12f);
        #pragma unroll
        for (int d = 0; d < kHD; d++) qr[d] *= inv;

        const float* comb = g_bias2 + ((long)((wi & 15) * kNH + h) * kN + r) * kN;
        float mx = scale + 16.f;
        float o[32];
        #pragma unroll
        for (int d = 0; d < kHD; d++) o[d] = 0.f;
        float sum = 0.f;
        for (int j = 0; j < kN; j++) {
            float tt = comb[j];
            #pragma unroll
            for (int d = 0; d < kHD; d++) tt = fmaf(qr[d], ks[j * 32 + d], tt);
            float e = __expf(tt - mx);
            sum += e;
            #pragma unroll
            for (int d = 0; d < kHD; d++) o[d] = fmaf(e, vs[j * 32 + d], o[d]);
        }
        float rs = 1.f / sum;
        float* op = g_scratch + 3 * kSLOT + ((long)(wi * kN + r)) * kC + h * kHD;
        #pragma unroll
        for (int d = 0; d < kHD; d++) op[d] = o[d] * rs;
    }
}

// ---------------------------------------------------------------------------
// LN + residual (optionally scattering window order -> image order)
// ---------------------------------------------------------------------------
template <bool SCATTER>
__global__ void __launch_bounds__(128) ln_res_kernel(
    const float* __restrict__ src, const float* __restrict__ resid,
    const float* __restrict__ gam, const float* __restrict__ bet,
    float* __restrict__ out) {
    int m = blockIdx.x;
    int dst = SCATTER ? win_src_row(m) : m;
    const float* row = src + (long)m * kC;
    int tid = threadIdx.x;
    float v0 = row[tid], v1 = row[tid + 128], v2 = row[tid + 256];
    float s = v0 + v1 + v2;
    float s2 = v0 * v0 + v1 * v1 + v2 * v2;
    #pragma unroll
    for (int o = 16; o > 0; o >>= 1) {
        s  += __shfl_xor_sync(0xffffffffu, s, o);
        s2 += __shfl_xor_sync(0xffffffffu, s2, o);
    }
    __shared__ float sh[8];
    int wid = tid >> 5, lane = tid & 31;
    if (lane == 0) { sh[wid] = s; sh[4 + wid] = s2; }
    __syncthreads();
    s  = sh[0] + sh[1] + sh[2] + sh[3];
    s2 = sh[4] + sh[5] + sh[6] + sh[7];
    float mean = s * (1.f / 384.f);
    float var = s2 * (1.f / 384.f) - mean * mean;
    float rstd = rsqrtf(var + 1e-5f);
    const float* rrow = resid + (long)dst * kC;
    float* orow = out + (long)dst * kC;
    orow[tid]       = rrow[tid]       + (v0 - mean) * rstd * gam[tid]       + bet[tid];
    orow[tid + 128] = rrow[tid + 128] + (v1 - mean) * rstd * gam[tid + 128] + bet[tid + 128];
    orow[tid + 256] = rrow[tid + 256] + (v2 - mean) * rstd * gam[tid + 256] + bet[tid + 256];
}

// ---------------------------------------------------------------------------
extern "C" void kernel_launch(void* const* d_in, const int* in_sizes, int n_in,
                              void* d_out, int out_size) {
    const float* x    = (const float*)d_in[0];
    const float* tab  = (const float*)d_in[1];
    const int*   rpi  = (const int*)  d_in[2];
    const float* mask = (const float*)d_in[3];
    const float* qkvw = (const float*)d_in[4];
    const float* qb   = (const float*)d_in[5];
    const float* vb   = (const float*)d_in[6];
    const float* lsc  = (const float*)d_in[7];
    const float* w1   = (const float*)d_in[8];
    const float* b1   = (const float*)d_in[9];
    const float* w2   = (const float*)d_in[10];
    const float* pw   = (const float*)d_in[11];
    const float* pb   = (const float*)d_in[12];
    const float* n1g  = (const float*)d_in[13];
    const float* n1b  = (const float*)d_in[14];
    const float* n2g  = (const float*)d_in[15];
    const float* n2b  = (const float*)d_in[16];
    const float* f1w  = (const float*)d_in[17];
    const float* f1b  = (const float*)d_in[18];
    const float* f2w  = (const float*)d_in[19];
    const float* f2b  = (const float*)d_in[20];
    float* out = (float*)d_out;

    float* scratch = nullptr;
    cudaGetSymbolAddress((void**)&scratch, g_scratch);

    // 1. CPB bias table + expansion (bias + mask combined)
    cpb_kernel<<<529, 512>>>(tab, w1, b1, w2);
    bias_expand_kernel<<<(16 * 12 * 144 * 144 + 255) / 256, 256>>>(rpi, mask);

    // 2. QKV GEMM (gathered A) -> q/k/v slots
    {
        dim3 g(1152 / 128, kM / 128);
        gemm_tf32<0, 1152, 384><<<g, 256>>>(x, qkvw, qb, vb, nullptr);
    }

    // 3. attention -> slot3
    attn_kernel<<<512 * kNH, 160>>>(lsc);

    // 4. proj GEMM: slot3 -> slot0
    {
        dim3 g(384 / 128, kM / 128);
        gemm_tf32<1, 384, 384><<<g, 256>>>(scratch + 3 * kSLOT, pw, pb, nullptr,
                                           scratch + 0 * kSLOT);
    }

    // 5. LN + residual + scatter: slot0 (+x) -> slot1 (x1)
    ln_res_kernel<true><<<kM, 128>>>(scratch + 0 * kSLOT, x, n1g, n1b,
                                     scratch + 1 * kSLOT);

    // 6. fc1 + GELU: slot1 -> slot2 (4 slots)
    {
        dim3 g(1536 / 128, kM / 128);
        gemm_tf32<2, 1536, 384><<<g, 256>>>(scratch + 1 * kSLOT, f1w, f1b, nullptr,
                                            scratch + 2 * kSLOT);
    }

    // 7. fc2: slot2 -> slot0
    {
        dim3 g(384 / 128, kM / 128);
        gemm_tf32<1, 384, 1536><<<g, 256>>>(scratch + 2 * kSLOT, f2w, f2b, nullptr,
                                            scratch + 0 * kSLOT);
    }

    // 8. final LN + residual -> out
    ln_res_kernel<false><<<kM, 128>>>(scratch + 0 * kSLOT, scratch + 1 * kSLOT,
                                      n2g, n2b, out);
}

// round 4
// speedup vs baseline: 2.6148x; 1.2576x over previous
#include <cuda_runtime.h>
#include <math.h>
#include <stdint.h>

// ---------------------------------------------------------------------------
// SwinV2 block: B=32, H=W=48, C=384, NH=12, HD=32, WS=12, N=144, SHIFT=6
// TF32 mma.sync GEMMs with cp.async 2-stage pipeline (sm_100 baseline ISA).
// ---------------------------------------------------------------------------
namespace {
constexpr int kH = 48;
constexpr int kW = 48;
constexpr int kC = 384;
constexpr int kNH = 12;
constexpr int kHD = 32;
constexpr int kWS = 12;
constexpr int kN = 144;
constexpr int kSHIFT = 6;
constexpr int kM = 73728;        // 512 windows * 144 tokens
constexpr long kSLOT = 28311552; // kM * kC

constexpr int STA = 36;   // A smem stride (floats): (36g+t)%32 = (4g+t)%32 bijective
constexpr int STB = 136;  // B smem stride (floats): (136t+g)%32 = (8t+g)%32 bijective
constexpr int A_STAGE = 128 * STA;       // 4608 floats (18432 B)
constexpr int B_STAGE = 32 * STB;        // 4352 floats (17408 B)
constexpr int SMEM_DYN = (2 * A_STAGE + 2 * B_STAGE) * 4;  // 71680 B

// tf32-rounded weight offsets (elements) in g_wtf  [k][n] layout, as in inputs
constexpr long OQKV = 0;        // 384 x 1152
constexpr long OPROJ = 442368;  // 384 x 384
constexpr long OFC1 = 589824;   // 384 x 1536
constexpr long OFC2 = 1179648;  // 1536 x 384
}

// scratch: slot0 = q / proj_out / fc2_out ; slot1 = k / x1
//          slot2 = v ; slot3 = attn_out ; fc1 out spans 2..5
__device__ float g_scratch[6 * 28311552ULL];
__device__ float g_btab[529 * 12];
__device__ float g_bias2[16 * 12 * 144 * 144];
__device__ float g_wtf[1769472];

__device__ __forceinline__ int win_src_row(int m) {
    int wi = m / kN, t = m - wi * kN;
    int b  = wi >> 4;
    int wh = (wi >> 2) & 3;
    int ww = wi & 3;
    int th = t / kWS, tw = t - th * kWS;
    int sh = wh * kWS + th + kSHIFT; if (sh >= kH) sh -= kH;
    int sw = ww * kWS + tw + kSHIFT; if (sw >= kW) sw -= kW;
    return (b * kH + sh) * kW + sw;
}

__device__ __forceinline__ uint32_t smem_u32(const void* p) {
    uint32_t a;
    asm("{ .reg .u64 t; cvta.to.shared.u64 t, %1; cvt.u32.u64 %0, t; }" : "=r"(a) : "l"(p));
    return a;
}
__device__ __forceinline__ uint32_t f2tf(float x) {
    uint32_t u; asm("cvt.rna.tf32.f32 %0, %1;" : "=r"(u) : "f"(x)); return u;
}
__device__ __forceinline__ void mma8(float* c, const uint32_t* a, const uint32_t* b) {
    asm volatile("mma.sync.aligned.m16n8k8.row.col.f32.tf32.tf32.f32 "
        "{%0,%1,%2,%3},{%4,%5,%6,%7},{%8,%9},{%0,%1,%2,%3};"
        : "+f"(c[0]), "+f"(c[1]), "+f"(c[2]), "+f"(c[3])
        : "r"(a[0]), "r"(a[1]), "r"(a[2]), "r"(a[3]), "r"(b[0]), "r"(b[1]));
}
__device__ __forceinline__ void cpa16(uint32_t dst, const void* src) {
    asm volatile("cp.async.ca.shared.global [%0], [%1], 16;" :: "r"(dst), "l"(src));
}
__device__ __forceinline__ void cpa_commit() {
    asm volatile("cp.async.commit_group;" ::: "memory");
}
template <int Nw>
__device__ __forceinline__ void cpa_wait() {
    asm volatile("cp.async.wait_group %0;" :: "n"(Nw) : "memory");
}

// ---------------------------------------------------------------------------
// K0: round weights to tf32 precision (stored as f32; mma truncation then exact)
// ---------------------------------------------------------------------------
__global__ void wtf32_kernel(const float* __restrict__ W, float* __restrict__ O, long n) {
    long i = (long)blockIdx.x * 256 + threadIdx.x;
    if (i < n) O[i] = __uint_as_float(f2tf(W[i]));
}

// ---------------------------------------------------------------------------
// K1: CPB MLP -> 16*sigmoid table (529 x 12)
// ---------------------------------------------------------------------------
__global__ void cpb_kernel(const float* __restrict__ table,
                           const float* __restrict__ w1,
                           const float* __restrict__ b1,
                           const float* __restrict__ w2) {
    __shared__ float hid[512];
    int e = blockIdx.x;
    int tid = threadIdx.x;
    float t0 = table[e * 2 + 0], t1 = table[e * 2 + 1];
    hid[tid] = fmaxf(0.f, fmaf(t0, w1[tid], fmaf(t1, w1[512 + tid], b1[tid])));
    __syncthreads();
    if (tid < 12) {
        float s = 0.f;
        #pragma unroll 8
        for (int i = 0; i < 512; i++) s = fmaf(hid[i], w2[i * 12 + tid], s);
        g_btab[e * 12 + tid] = 16.f / (1.f + expf(-s));
    }
}

__global__ void bias_expand_kernel(const int* __restrict__ rpi,
                                   const float* __restrict__ mask) {
    int idx = blockIdx.x * 256 + threadIdx.x;
    if (idx >= 16 * 12 * 144 * 144) return;
    int rj = idx % (144 * 144);
    int wh = idx / (144 * 144);
    int h = wh % 12, wt = wh / 12;
    g_bias2[idx] = g_btab[rpi[rj] * 12 + h] + mask[wt * 144 * 144 + rj];
}

// ---------------------------------------------------------------------------
// TF32 GEMM v2: 128x128 tile, BK=32, 2-stage cp.async pipeline, 256 threads,
// 8 warps each 32x64 via mma.sync.m16n8k8.tf32.  B pre-rounded to tf32.
// MODE 0: qkv (A gathered; scatter epilogue + q/v bias)
// MODE 1: bias ; MODE 2: bias + exact GELU
// ---------------------------------------------------------------------------
template <int MODE, int Ncols, int Kdim>
__global__ void __launch_bounds__(256, 2) gemm_tf32v2(
    const float* __restrict__ A_in, const float* __restrict__ Wt,
    const float* __restrict__ bias, const float* __restrict__ bias2,
    float* __restrict__ Cout) {
    extern __shared__ float smem[];
    float* As[2] = { smem, smem + A_STAGE };
    float* Bs[2] = { smem + 2 * A_STAGE, smem + 2 * A_STAGE + B_STAGE };
    uint32_t sbA[2] = { smem_u32(As[0]), smem_u32(As[1]) };
    uint32_t sbB[2] = { smem_u32(Bs[0]), smem_u32(Bs[1]) };

    int tid = threadIdx.x;
    int bx = blockIdx.x, by = blockIdx.y;
    int warp = tid >> 5, lane = tid & 31;
    int g = lane >> 2, t = lane & 3;
    int wm = (warp & 3) * 32, wn = (warp >> 2) * 64;
    constexpr int NCHUNK = Kdim / 32;

    // A rows for this thread (4 rows: tid>>3 + 32*i), gathered in MODE 0
    long arows[4];
    int aseg = tid & 7;
    #pragma unroll
    for (int i = 0; i < 4; i++) {
        int gr = by * 128 + (tid >> 3) + 32 * i;
        arows[i] = (MODE == 0) ? (long)win_src_row(gr) : (long)gr;
    }
    int brow = tid >> 5;          // +32*i/? B: row = (tid+256i)>>5 = brow + 8*i
    int bc4 = tid & 31;

    auto load_stage = [&](int s, int kc) {
        #pragma unroll
        for (int i = 0; i < 4; i++) {
            int row = (tid >> 3) + 32 * i;
            cpa16(sbA[s] + row * (STA * 4) + aseg * 16,
                  A_in + arows[i] * Kdim + kc + aseg * 4);
        }
        #pragma unroll
        for (int i = 0; i < 4; i++) {
            int row = brow + 8 * i;
            cpa16(sbB[s] + row * (STB * 4) + bc4 * 16,
                  Wt + (long)(kc + row) * Ncols + bx * 128 + bc4 * 4);
        }
    };

    float acc[2][8][4];
    #pragma unroll
    for (int i = 0; i < 2; i++)
        #pragma unroll
        for (int j = 0; j < 8; j++)
            #pragma unroll
            for (int q = 0; q < 4; q++) acc[i][j][q] = 0.f;

    load_stage(0, 0);
    cpa_commit();

    for (int c = 0; c < NCHUNK; c++) {
        if (c + 1 < NCHUNK) load_stage((c + 1) & 1, (c + 1) * 32);
        cpa_commit();
        cpa_wait<1>();
        __syncthreads();
        const float* Ac = As[c & 1];
        const float* Bc = Bs[c & 1];
        #pragma unroll
        for (int kk = 0; kk < 32; kk += 8) {
            uint32_t af[2][4];
            #pragma unroll
            for (int mt = 0; mt < 2; mt++) {
                const float* ap = Ac + (wm + mt * 16 + g) * STA + kk + t;
                af[mt][0] = f2tf(ap[0]);
                af[mt][1] = f2tf(ap[8 * STA]);
                af[mt][2] = f2tf(ap[4]);
                af[mt][3] = f2tf(ap[8 * STA + 4]);
            }
            uint32_t bf[8][2];
            #pragma unroll
            for (int nt = 0; nt < 8; nt++) {
                const float* bp = Bc + (kk + t) * STB + wn + nt * 8 + g;
                bf[nt][0] = __float_as_uint(bp[0]);
                bf[nt][1] = __float_as_uint(bp[4 * STB]);
            }
            #pragma unroll
            for (int mt = 0; mt < 2; mt++)
                #pragma unroll
                for (int nt = 0; nt < 8; nt++)
                    mma8(acc[mt][nt], af[mt], bf[nt]);
        }
        __syncthreads();
    }

    // ---- epilogue ----
    int gr = by * 128 + wm + g;
    int gc = bx * 128 + wn + 2 * t;
    #pragma unroll
    for (int mt = 0; mt < 2; mt++) {
        int r0 = gr + mt * 16;
        #pragma unroll
        for (int nt = 0; nt < 8; nt++) {
            int c0 = gc + nt * 8;
            if (MODE == 0) {
                #pragma unroll
                for (int e = 0; e < 4; e++) {
                    int row = r0 + (e >> 1) * 8;
                    int col = c0 + (e & 1);
                    int wi = row / kN, tk = row - wi * kN;
                    int part = col / kC, cc = col - part * kC;
                    float bv = (part == 0) ? bias[cc] : (part == 2 ? bias2[cc] : 0.f);
                    g_scratch[(long)part * kSLOT +
                              (((long)(wi * kNH + (cc >> 5))) * kN + tk) * kHD + (cc & 31)]
                        = acc[mt][nt][e] + bv;
                }
            } else {
                float b0 = bias[c0], b1 = bias[c0 + 1];
                float2 v;
                v.x = acc[mt][nt][0] + b0; v.y = acc[mt][nt][1] + b1;
                if (MODE == 2) {
                    v.x = 0.5f * v.x * (1.f + erff(v.x * 0.70710678f));
                    v.y = 0.5f * v.y * (1.f + erff(v.y * 0.70710678f));
                }
                *(float2*)&Cout[(long)r0 * Ncols + c0] = v;
                v.x = acc[mt][nt][2] + b0; v.y = acc[mt][nt][3] + b1;
                if (MODE == 2) {
                    v.x = 0.5f * v.x * (1.f + erff(v.x * 0.70710678f));
                    v.y = 0.5f * v.y * (1.f + erff(v.y * 0.70710678f));
                }
                *(float2*)&Cout[(long)(r0 + 8) * Ncols + c0] = v;
            }
        }
    }
}

// ---------------------------------------------------------------------------
// K3: cosine attention, one block per (window, head). 160 threads, 1 row each.
// float4-vectorized k/v smem access. Fixed stabilizer mx = scale + 16.
// ---------------------------------------------------------------------------
__global__ void __launch_bounds__(160) attn_kernel(const float* __restrict__ lsc) {
    __shared__ float4 ks4[144 * 8];
    __shared__ float4 vs4[144 * 8];
    int bh = blockIdx.x;
    int wi = bh / kNH, h = bh - wi * kNH;
    int tid = threadIdx.x;

    const float4* qg = (const float4*)(g_scratch + 0 * kSLOT + (long)bh * kN * kHD);
    const float4* kg = (const float4*)(g_scratch + 1 * kSLOT + (long)bh * kN * kHD);
    const float4* vg = (const float4*)(g_scratch + 2 * kSLOT + (long)bh * kN * kHD);

    for (int i = tid; i < 144 * 8; i += 160) {
        ks4[i] = kg[i];
        vs4[i] = vg[i];
    }
    __syncthreads();
    if (tid < kN) {
        float s = 0.f;
        float4 kr[8];
        #pragma unroll
        for (int d = 0; d < 8; d++) {
            kr[d] = ks4[tid * 8 + d];
            s += kr[d].x * kr[d].x + kr[d].y * kr[d].y + kr[d].z * kr[d].z + kr[d].w * kr[d].w;
        }
        float inv = 1.f / fmaxf(sqrtf(s), 1e-12f);
        #pragma unroll
        for (int d = 0; d < 8; d++) {
            kr[d].x *= inv; kr[d].y *= inv; kr[d].z *= inv; kr[d].w *= inv;
            ks4[tid * 8 + d] = kr[d];
        }
    }
    __syncthreads();

    if (tid < kN) {
        int r = tid;
        float scale = __expf(fminf(lsc[h], 4.605170185988092f));
        float4 qr[8];
        float s = 0.f;
        #pragma unroll
        for (int d = 0; d < 8; d++) {
            qr[d] = qg[r * 8 + d];
            s += qr[d].x * qr[d].x + qr[d].y * qr[d].y + qr[d].z * qr[d].z + qr[d].w * qr[d].w;
        }
        float inv = scale / fmaxf(sqrtf(s), 1e-12f);
        #pragma unroll
        for (int d = 0; d < 8; d++) {
            qr[d].x *= inv; qr[d].y *= inv; qr[d].z *= inv; qr[d].w *= inv;
        }

        const float* comb = g_bias2 + ((long)((wi & 15) * kNH + h) * kN + r) * kN;
        float mx = scale + 16.f;
        float4 o[8];
        #pragma unroll
        for (int d = 0; d < 8; d++) o[d] = make_float4(0.f, 0.f, 0.f, 0.f);
        float sum = 0.f;
        for (int j = 0; j < kN; j++) {
            float tt = comb[j];
            #pragma unroll
            for (int d = 0; d < 8; d++) {
                float4 kv = ks4[j * 8 + d];
                tt = fmaf(qr[d].x, kv.x, tt);
                tt = fmaf(qr[d].y, kv.y, tt);
                tt = fmaf(qr[d].z, kv.z, tt);
                tt = fmaf(qr[d].w, kv.w, tt);
            }
            float e = __expf(tt - mx);
            sum += e;
            #pragma unroll
            for (int d = 0; d < 8; d++) {
                float4 vv = vs4[j * 8 + d];
                o[d].x = fmaf(e, vv.x, o[d].x);
                o[d].y = fmaf(e, vv.y, o[d].y);
                o[d].z = fmaf(e, vv.z, o[d].z);
                o[d].w = fmaf(e, vv.w, o[d].w);
            }
        }
        float rs = 1.f / sum;
        float4* op = (float4*)(g_scratch + 3 * kSLOT + ((long)(wi * kN + r)) * kC + h * kHD);
        #pragma unroll
        for (int d = 0; d < 8; d++) {
            o[d].x *= rs; o[d].y *= rs; o[d].z *= rs; o[d].w *= rs;
            op[d] = o[d];
        }
    }
}

// ---------------------------------------------------------------------------
// LN + residual (optionally scattering window order -> image order)
// ---------------------------------------------------------------------------
template <bool SCATTER>
__global__ void __launch_bounds__(128) ln_res_kernel(
    const float* __restrict__ src, const float* __restrict__ resid,
    const float* __restrict__ gam, const float* __restrict__ bet,
    float* __restrict__ out) {
    int m = blockIdx.x;
    int dst = SCATTER ? win_src_row(m) : m;
    const float* row = src + (long)m * kC;
    int tid = threadIdx.x;
    float v0 = row[tid], v1 = row[tid + 128], v2 = row[tid + 256];
    float s = v0 + v1 + v2;
    float s2 = v0 * v0 + v1 * v1 + v2 * v2;
    #pragma unroll
    for (int o = 16; o > 0; o >>= 1) {
        s  += __shfl_xor_sync(0xffffffffu, s, o);
        s2 += __shfl_xor_sync(0xffffffffu, s2, o);
    }
    __shared__ float sh[8];
    int wid = tid >> 5, lane = tid & 31;
    if (lane == 0) { sh[wid] = s; sh[4 + wid] = s2; }
    __syncthreads();
    s  = sh[0] + sh[1] + sh[2] + sh[3];
    s2 = sh[4] + sh[5] + sh[6] + sh[7];
    float mean = s * (1.f / 384.f);
    float var = s2 * (1.f / 384.f) - mean * mean;
    float rstd = rsqrtf(var + 1e-5f);
    const float* rrow = resid + (long)dst * kC;
    float* orow = out + (long)dst * kC;
    orow[tid]       = rrow[tid]       + (v0 - mean) * rstd * gam[tid]       + bet[tid];
    orow[tid + 128] = rrow[tid + 128] + (v1 - mean) * rstd * gam[tid + 128] + bet[tid + 128];
    orow[tid + 256] = rrow[tid + 256] + (v2 - mean) * rstd * gam[tid + 256] + bet[tid + 256];
}

// ---------------------------------------------------------------------------
extern "C" void kernel_launch(void* const* d_in, const int* in_sizes, int n_in,
                              void* d_out, int out_size) {
    const float* x    = (const float*)d_in[0];
    const float* tab  = (const float*)d_in[1];
    const int*   rpi  = (const int*)  d_in[2];
    const float* mask = (const float*)d_in[3];
    const float* qkvw = (const float*)d_in[4];
    const float* qb   = (const float*)d_in[5];
    const float* vb   = (const float*)d_in[6];
    const float* lsc  = (const float*)d_in[7];
    const float* w1   = (const float*)d_in[8];
    const float* b1   = (const float*)d_in[9];
    const float* w2   = (const float*)d_in[10];
    const float* pw   = (const float*)d_in[11];
    const float* pb   = (const float*)d_in[12];
    const float* n1g  = (const float*)d_in[13];
    const float* n1b  = (const float*)d_in[14];
    const float* n2g  = (const float*)d_in[15];
    const float* n2b  = (const float*)d_in[16];
    const float* f1w  = (const float*)d_in[17];
    const float* f1b  = (const float*)d_in[18];
    const float* f2w  = (const float*)d_in[19];
    const float* f2b  = (const float*)d_in[20];
    float* out = (float*)d_out;

    float* scratch = nullptr;
    cudaGetSymbolAddress((void**)&scratch, g_scratch);
    float* wtf = nullptr;
    cudaGetSymbolAddress((void**)&wtf, g_wtf);

    cudaFuncSetAttribute(gemm_tf32v2<0, 1152, 384>, cudaFuncAttributeMaxDynamicSharedMemorySize, SMEM_DYN);
    cudaFuncSetAttribute(gemm_tf32v2<1, 384, 384>,  cudaFuncAttributeMaxDynamicSharedMemorySize, SMEM_DYN);
    cudaFuncSetAttribute(gemm_tf32v2<2, 1536, 384>, cudaFuncAttributeMaxDynamicSharedMemorySize, SMEM_DYN);
    cudaFuncSetAttribute(gemm_tf32v2<1, 384, 1536>, cudaFuncAttributeMaxDynamicSharedMemorySize, SMEM_DYN);

    // 0. pre-round weights to tf32 precision (layout unchanged [k][n])
    wtf32_kernel<<<(442368 + 255) / 256, 256>>>(qkvw, wtf + OQKV, 442368);
    wtf32_kernel<<<(147456 + 255) / 256, 256>>>(pw,  wtf + OPROJ, 147456);
    wtf32_kernel<<<(589824 + 255) / 256, 256>>>(f1w, wtf + OFC1,  589824);
    wtf32_kernel<<<(589824 + 255) / 256, 256>>>(f2w, wtf + OFC2,  589824);

    // 1. CPB bias table + expansion (bias + mask combined)
    cpb_kernel<<<529, 512>>>(tab, w1, b1, w2);
    bias_expand_kernel<<<(16 * 12 * 144 * 144 + 255) / 256, 256>>>(rpi, mask);

    // 2. QKV GEMM (gathered A) -> q/k/v slots
    gemm_tf32v2<0, 1152, 384><<<dim3(9, 576), 256, SMEM_DYN>>>(
        x, wtf + OQKV, qb, vb, nullptr);

    // 3. attention -> slot3
    attn_kernel<<<512 * kNH, 160>>>(lsc);

    // 4. proj GEMM: slot3 -> slot0
    gemm_tf32v2<1, 384, 384><<<dim3(3, 576), 256, SMEM_DYN>>>(
        scratch + 3 * kSLOT, wtf + OPROJ, pb, nullptr, scratch + 0 * kSLOT);

    // 5. LN + residual + scatter: slot0 (+x) -> slot1 (x1)
    ln_res_kernel<true><<<kM, 128>>>(scratch + 0 * kSLOT, x, n1g, n1b, scratch + 1 * kSLOT);

    // 6. fc1 + GELU: slot1 -> slot2 (4 slots)
    gemm_tf32v2<2, 1536, 384><<<dim3(12, 576), 256, SMEM_DYN>>>(
        scratch + 1 * kSLOT, wtf + OFC1, f1b, nullptr, scratch + 2 * kSLOT);

    // 7. fc2: slot2 -> slot0
    gemm_tf32v2<1, 384, 1536><<<dim3(3, 576), 256, SMEM_DYN>>>(
        scratch + 2 * kSLOT, wtf + OFC2, f2b, nullptr, scratch + 0 * kSLOT);

    // 8. final LN + residual -> out
    ln_res_kernel<false><<<kM, 128>>>(scratch + 0 * kSLOT, scratch + 1 * kSLOT,
                                      n2g, n2b, out);
}